// round 8
// baseline (speedup 1.0000x reference)
#include <cuda_runtime.h>

typedef unsigned long long u64;

#define NQ    12
#define DEPTH 4
#define NPAR  144
#define THREADS 512

__device__ __forceinline__ u64 f2fma(u64 a, u64 b, u64 c) {
    u64 d; asm("fma.rn.f32x2 %0,%1,%2,%3;" : "=l"(d) : "l"(a), "l"(b), "l"(c)); return d;
}
__device__ __forceinline__ u64 f2mul(u64 a, u64 b) {
    u64 d; asm("mul.rn.f32x2 %0,%1,%2;" : "=l"(d) : "l"(a), "l"(b)); return d;
}
__device__ __forceinline__ u64 pk(float lo, float hi) {
    u64 r; asm("mov.b64 %0,{%1,%2};" : "=l"(r) : "f"(lo), "f"(hi)); return r;
}
__device__ __forceinline__ void upk(u64 v, float& lo, float& hi) {
    asm("mov.b64 {%0,%1},%2;" : "=f"(lo), "=f"(hi) : "l"(v));
}
__device__ __forceinline__ u64 f2swap(u64 v) {
    float lo, hi; upk(v, lo, hi); return pk(hi, lo);
}

struct c2 { float r, i; };
__device__ __forceinline__ c2 cmul(c2 a, c2 b) {
    c2 o; o.r = a.r * b.r - a.i * b.i; o.i = a.r * b.i + a.i * b.r; return o;
}

// CNOT-ring linear map (reference gate order)
__device__ __forceinline__ int perm12(int s) {
    int d = s;
    #pragma unroll
    for (int q = 0; q < 12; q++) {
        int bc = 11 - q, bt = 11 - ((q + 1) % 12);
        d ^= ((d >> bc) & 1) << bt;
    }
    return d;
}
// physical float address swizzle (GF2-linear, keeps (i, i^1) pairs unit-aligned)
__device__ __forceinline__ int Fmap(int i) {
    return i ^ (((i >> 6) & 1) << 1) ^ (((i >> 7) & 1) << 2) ^ (((i >> 8) & 1) << 3);
}

#define LOADC(gi)                                                     \
    const u64* rec = gpk + (gi) * 12;                                 \
    ulonglong2 q01 = *(const ulonglong2*)(rec);                       \
    ulonglong2 q23 = *(const ulonglong2*)(rec + 2);                   \
    ulonglong2 q45 = *(const ulonglong2*)(rec + 4);                   \
    u64 PX = q01.x, PY = q01.y, NY = q23.x, PZ = q23.y;               \
    u64 NZ = q45.x, PW = q45.y, NW = rec[6];

#define PACK_GATE(gi)                                                 \
    {                                                                 \
        const u64* rec = gpk + (gi) * 12;                             \
        u64 PX = rec[0], PWv = rec[5], NWv = rec[6];                  \
        ulonglong2 mm = *(const ulonglong2*)(rec + 8);                \
        u64 MY = mm.x, MYr = mm.y, MZ = rec[10];                      \
        _Pragma("unroll")                                             \
        for (int p = 0; p < 4; p++) {                                 \
            u64 R = Re[p], I = Im[p];                                 \
            u64 Rs = f2swap(R), Is = f2swap(I);                       \
            Re[p] = f2fma(NWv, Is, f2fma(MZ, Rs, f2fma(MY,  I, f2mul(PX, R)))); \
            Im[p] = f2fma(PWv, Rs, f2fma(MZ, Is, f2fma(MYr, R, f2mul(PX, I)))); \
        }                                                             \
    }

#define REGPAIR_GATE(gi, mask)                                        \
    {                                                                 \
        LOADC(gi)                                                     \
        _Pragma("unroll")                                             \
        for (int p0 = 0; p0 < 4; p0++) {                              \
            if (p0 & (mask)) continue;                                \
            const int p1 = p0 | (mask);                               \
            u64 aR = Re[p0], aI = Im[p0], bR = Re[p1], bI = Im[p1];   \
            Re[p0] = f2fma(NW, bI, f2fma(PZ, bR, f2fma(NY, aI, f2mul(PX, aR)))); \
            Im[p0] = f2fma(PW, bR, f2fma(PZ, bI, f2fma(PY, aR, f2mul(PX, aI)))); \
            Re[p1] = f2fma(NW, aI, f2fma(NZ, aR, f2fma(PY, bI, f2mul(PX, bR)))); \
            Im[p1] = f2fma(PW, aR, f2fma(NZ, aI, f2fma(NY, bR, f2mul(PX, bI)))); \
        }                                                             \
    }

#define SHUF_GATE(gi, lm, mybit)                                      \
    {                                                                 \
        LOADC(gi)                                                     \
        u64 Ya = (mybit) ? PY : NY;                                   \
        u64 Yb = (mybit) ? NY : PY;                                   \
        u64 Zc = (mybit) ? NZ : PZ;                                   \
        _Pragma("unroll")                                             \
        for (int p = 0; p < 4; p++) {                                 \
            u64 mR = Re[p], mI = Im[p];                               \
            u64 oR = __shfl_xor_sync(0xffffffffu, mR, lm);            \
            u64 oI = __shfl_xor_sync(0xffffffffu, mI, lm);            \
            Re[p] = f2fma(NW, oI, f2fma(Zc, oR, f2fma(Ya, mI, f2mul(PX, mR)))); \
            Im[p] = f2fma(PW, oR, f2fma(Zc, oI, f2fma(Yb, mR, f2mul(PX, mI)))); \
        }                                                             \
    }

__global__ __launch_bounds__(THREADS, 2)
void qgen_kernel(const float* __restrict__ noise,
                 const float* __restrict__ W1, const float* __restrict__ b1,
                 const float* __restrict__ W2, const float* __restrict__ b2,
                 const float* __restrict__ W3, const float* __restrict__ b3,
                 const float* __restrict__ W4, const float* __restrict__ b4,
                 float* __restrict__ out)
{
    __shared__ __align__(16) u64 exR64[2048];
    __shared__ __align__(16) u64 exI64[2048];
    __shared__ __align__(16) u64 gpk[48 * 12];
    __shared__ float2 s_v[12][2];
    __shared__ float s_nz[12];
    __shared__ float s_h[64];
    __shared__ float s_par[NPAR];
    __shared__ float s_meas[12];
    __shared__ float s_wsum[16][12];
    __shared__ float s_h2[64];

    float* exRf = (float*)exR64;
    float* exIf = (float*)exI64;

    const int t   = threadIdx.x;
    const int bId = blockIdx.x;

    if (t < 12) s_nz[t] = noise[bId * 12 + t];
    __syncthreads();

    if (t < 64) {
        float acc = b1[t];
        #pragma unroll
        for (int m = 0; m < 12; m++) acc += s_nz[m] * W1[m * 64 + t];
        s_h[t] = tanhf(acc);
    }
    __syncthreads();

    if (t < NPAR) {
        float acc = b2[t];
        #pragma unroll 8
        for (int j = 0; j < 64; j++) acc += s_h[j] * W2[j * NPAR + t];
        s_par[t] = acc;
    }
    __syncthreads();

    // U = RZ(c)RY(b)RX(a) = [[gx+igy, gz+igw],[-(gz-igw), gx-igy]]
    if (t < 48) {
        float a = s_par[t * 3 + 0], b = s_par[t * 3 + 1], c = s_par[t * 3 + 2];
        float ca, sa, cb, sb, cc, sc;
        sincosf(0.5f * a, &sa, &ca);
        sincosf(0.5f * b, &sb, &cb);
        sincosf(0.5f * c, &sc, &cc);
        float x = cb * ca, y = sb * sa, z = sb * ca, w = cb * sa;
        float gx =  cc * x + sc * y;
        float gy =  cc * y - sc * x;
        float gz = -(cc * z + sc * w);
        float gw =  sc * z - cc * w;
        u64* r = gpk + t * 12;
        r[0]  = pk(gx, gx);  r[1] = pk(gy, gy);  r[2] = pk(-gy, -gy);
        r[3]  = pk(gz, gz);  r[4] = pk(-gz, -gz);
        r[5]  = pk(gw, gw);  r[6] = pk(-gw, -gw);
        r[8]  = pk(-gy, gy); r[9] = pk(gy, -gy); r[10] = pk(gz, -gz);
        if (t < 12) {
            s_v[t][0] = make_float2(gx, gy);
            s_v[t][1] = make_float2(-gz, gw);
        }
    }

    // ---- addresses ----
    // Layout A: thread = i[11:3]; regs p = i[2:1]; pack = i0. Unit base (p=0):
    const int VA = (t << 2) ^ ((t >> 3) & 1) ^ (((t >> 4) & 1) << 1)
                 ^ (((t >> 5) & 1) << 2);
    // Layout B: lane = i[8:4] = t[4:0], upper = i[3:0] = t[8:5], regs = i[11:10], pack = i9
    const int ibB = ((t & 31) << 4) | (t >> 5);
    const int FbB = Fmap(ibB);
    const int pMb = Fmap(perm12(ibB));

    __syncthreads();   // gpk + s_v visible

    // ---- layer 0 (gates + first ring) via product-state synthesis ----
    // amp_A[i] = prod_q v_q[x_q]; x_q = i_{11-q}^i_{12-q} (q>=2),
    // x_0 = i11^i0, x_1 = i10^i11^i0
    u64 Re[4], Im[4];
    {
        #define LV(q, e) ({ float2 f = s_v[q][(e) & 1]; c2 z; z.r = f.x; z.i = f.y; z; })
        c2 C = cmul(cmul(cmul(LV(2, (t >> 6) ^ (t >> 7)), LV(3, (t >> 5) ^ (t >> 6))),
                         cmul(LV(4, (t >> 4) ^ (t >> 5)), LV(5, (t >> 3) ^ (t >> 4)))),
                    cmul(cmul(LV(6, (t >> 2) ^ (t >> 3)), LV(7, (t >> 1) ^ (t >> 2))),
                         LV(8, t ^ (t >> 1))));
        const int t8 = (t >> 8) & 1, t78 = ((t >> 7) ^ (t >> 8)) & 1, t0 = t & 1;
        c2 P0 = cmul(LV(0, t8),     LV(1, t78));
        c2 P1 = cmul(LV(0, t8 ^ 1), LV(1, t78 ^ 1));
        c2 Q00 = cmul(LV(11, 0), P0);   // (r0=0,i0=0)
        c2 Q01 = cmul(LV(11, 1), P1);   // (0,1)
        c2 Q10 = cmul(LV(11, 1), P0);   // (1,0)
        c2 Q11 = cmul(LV(11, 0), P1);   // (1,1)
        c2 W0 = cmul(C, LV(9, t0));
        c2 W1 = cmul(C, LV(9, t0 ^ 1));
        c2 X00 = cmul(W0, LV(10, 0));
        c2 X01 = cmul(W0, LV(10, 1));
        c2 X10 = cmul(W1, LV(10, 1));
        c2 X11 = cmul(W1, LV(10, 0));
        #undef LV
        c2 lo, hi;
        lo = cmul(X00, Q00); hi = cmul(X00, Q01);
        Re[0] = pk(lo.r, hi.r); Im[0] = pk(lo.i, hi.i);
        lo = cmul(X01, Q10); hi = cmul(X01, Q11);
        Re[1] = pk(lo.r, hi.r); Im[1] = pk(lo.i, hi.i);
        lo = cmul(X10, Q00); hi = cmul(X10, Q01);
        Re[2] = pk(lo.r, hi.r); Im[2] = pk(lo.i, hi.i);
        lo = cmul(X11, Q10); hi = cmul(X11, Q11);
        Re[3] = pk(lo.r, hi.r); Im[3] = pk(lo.i, hi.i);
    }

    // ---- layers 1..3 ----
    #pragma unroll 1
    for (int l = 1; l < DEPTH; l++) {
        // A section: q11 pack, q10/q9 reg-pair, q8..q4 shuffles (lane bits 0..4)
        PACK_GATE(l * 12 + 11)
        REGPAIR_GATE(l * 12 + 10, 1)
        REGPAIR_GATE(l * 12 + 9, 2)
        #pragma unroll
        for (int tb = 0; tb < 5; tb++) {
            SHUF_GATE(l * 12 + 8 - tb, 1 << tb, (t >> tb) & 1)
        }

        // transpose A -> B
        __syncthreads();
        #pragma unroll
        for (int p = 0; p < 4; p++) {
            exR64[VA ^ p] = Re[p];
            exI64[VA ^ p] = Im[p];
        }
        __syncthreads();
        #pragma unroll
        for (int p = 0; p < 4; p++) {
            const int f0 = FbB ^ (p << 10);
            const int f1 = f0 ^ (1 << 9);
            Re[p] = pk(exRf[f0], exRf[f1]);
            Im[p] = pk(exIf[f0], exIf[f1]);
        }

        // B section: q3 shuffle (lane bit 4), q2 pack, q1/q0 reg-pair
        SHUF_GATE(l * 12 + 3, 16, (t >> 4) & 1)
        PACK_GATE(l * 12 + 2)
        REGPAIR_GATE(l * 12 + 1, 1)
        REGPAIR_GATE(l * 12 + 0, 2)

        if (l == DEPTH - 1) break;   // final ring folded into measurement signs

        // CNOT-ring perm scatter B -> A
        __syncthreads();
        #pragma unroll
        for (int p = 0; p < 4; p++) {
            float r0, r1, i0v, i1v;
            upk(Re[p], r0, r1);
            upk(Im[p], i0v, i1v);
            const int a0 = pMb ^ Fmap(perm12((2 * p)     << 9));
            const int a1 = pMb ^ Fmap(perm12((2 * p + 1) << 9));
            exRf[a0] = r0;  exIf[a0] = i0v;
            exRf[a1] = r1;  exIf[a1] = i1v;
        }
        __syncthreads();
        #pragma unroll
        for (int p = 0; p < 4; p++) {
            Re[p] = exR64[VA ^ p];
            Im[p] = exI64[VA ^ p];
        }
    }

    // ---- <Z_q> in layout B, final ring folded into suffix-parity signs ----
    // s bits: s[8:4]=t[4:0], s[3:0]=t[8:5], s11=p bit1, s10=p bit0, s9=pack
    float U0 = 0.f, U1 = 0.f, U2 = 0.f;
    #pragma unroll
    for (int p = 0; p < 4; p++) {
        u64 p2 = f2fma(Im[p], Im[p], f2mul(Re[p], Re[p]));
        float pl, ph; upk(p2, pl, ph);
        float sm = pl + ph, df = pl - ph;
        float s2 = (__popc(p & 3) & 1) ? -1.f : 1.f;
        U0 += (p & 1) ? -df : df;
        U1 += s2 * sm;
        U2 += s2 * df;
    }
    float c[12];
    c[0] = (__popc(t & 0x1FF) & 1) ? -U0 : U0;
    c[1] = U1;
    c[2] = U2;
    {
        const int masks[9] = {0x010, 0x018, 0x01C, 0x01E, 0x01F,
                              0x11F, 0x19F, 0x1DF, 0x1FF};
        #pragma unroll
        for (int q = 3; q < 12; q++)
            c[q] = (__popc(t & masks[q - 3]) & 1) ? -U2 : U2;
    }

    #pragma unroll
    for (int s = 16; s >= 1; s >>= 1) {
        #pragma unroll
        for (int q = 0; q < 12; q++)
            c[q] += __shfl_xor_sync(0xffffffffu, c[q], s);
    }
    const int warp = t >> 5, lane = t & 31;
    if (lane == 0) {
        #pragma unroll
        for (int q = 0; q < 12; q++) s_wsum[warp][q] = c[q];
    }
    __syncthreads();
    if (t < 12) {
        float m = 0.f;
        #pragma unroll
        for (int w = 0; w < 16; w++) m += s_wsum[w][t];
        s_meas[t] = m;
    }
    __syncthreads();

    if (t < 64) {
        float acc = b3[t];
        #pragma unroll
        for (int q = 0; q < 12; q++) acc += s_meas[q] * W3[q * 64 + t];
        s_h2[t] = tanhf(acc);
    }
    __syncthreads();

    if (t < 2) {
        float acc = b4[t];
        #pragma unroll 8
        for (int j = 0; j < 64; j++) acc += s_h2[j] * W4[j * 2 + t];
        out[bId * 2 + t] = acc;
    }
}

extern "C" void kernel_launch(void* const* d_in, const int* in_sizes, int n_in,
                              void* d_out, int out_size)
{
    (void)n_in; (void)out_size;
    const float* noise = (const float*)d_in[0];
    const float* W1    = (const float*)d_in[1];
    const float* b1    = (const float*)d_in[2];
    const float* W2    = (const float*)d_in[3];
    const float* b2    = (const float*)d_in[4];
    const float* W3    = (const float*)d_in[5];
    const float* b3    = (const float*)d_in[6];
    const float* W4    = (const float*)d_in[7];
    const float* b4    = (const float*)d_in[8];
    float* out = (float*)d_out;

    const int B = in_sizes[0] / NQ;
    qgen_kernel<<<B, THREADS>>>(noise, W1, b1, W2, b2, W3, b3, W4, b4, out);
}

// round 9
// speedup vs baseline: 1.2003x; 1.2003x over previous
#include <cuda_runtime.h>

typedef unsigned long long u64;

#define NQ    12
#define DEPTH 4
#define NPAR  144
#define THREADS 256

__device__ __forceinline__ u64 f2fma(u64 a, u64 b, u64 c) {
    u64 d; asm("fma.rn.f32x2 %0,%1,%2,%3;" : "=l"(d) : "l"(a), "l"(b), "l"(c)); return d;
}
__device__ __forceinline__ u64 f2mul(u64 a, u64 b) {
    u64 d; asm("mul.rn.f32x2 %0,%1,%2;" : "=l"(d) : "l"(a), "l"(b)); return d;
}
__device__ __forceinline__ u64 pk(float lo, float hi) {
    u64 r; asm("mov.b64 %0,{%1,%2};" : "=l"(r) : "f"(lo), "f"(hi)); return r;
}
__device__ __forceinline__ void upk(u64 v, float& lo, float& hi) {
    asm("mov.b64 {%0,%1},%2;" : "=f"(lo), "=f"(hi) : "l"(v));
}
__device__ __forceinline__ u64 f2swap(u64 v) {
    float lo, hi; upk(v, lo, hi); return pk(hi, lo);
}

struct c2 { float r, i; };
__device__ __forceinline__ c2 cmul(c2 a, c2 b) {
    c2 o; o.r = a.r * b.r - a.i * b.i; o.i = a.r * b.i + a.i * b.r; return o;
}

// CNOT-ring linear map (reference gate order): suffix-XOR
__device__ __forceinline__ int perm12(int s) {
    int d = s;
    #pragma unroll
    for (int q = 0; q < 12; q++) {
        int bc = 11 - q, bt = 11 - ((q + 1) % 12);
        d ^= ((d >> bc) & 1) << bt;
    }
    return d;
}
// physical float swizzle: F(i) = i ^ (i5<<1) ^ (i6<<2) ^ (i7<<3) ^ (i8<<4)
__device__ __forceinline__ int Fful(int i) {
    return i ^ (((i >> 5) & 1) << 1) ^ (((i >> 6) & 1) << 2)
             ^ (((i >> 7) & 1) << 3) ^ (((i >> 8) & 1) << 4);
}

#define LOADC(gi)                                                     \
    const u64* rec = gpk + (gi) * 12;                                 \
    ulonglong2 q01 = *(const ulonglong2*)(rec);                       \
    ulonglong2 q23 = *(const ulonglong2*)(rec + 2);                   \
    ulonglong2 q45 = *(const ulonglong2*)(rec + 4);                   \
    u64 PX = q01.x, PY = q01.y, NY = q23.x, PZ = q23.y;               \
    u64 NZ = q45.x, PW = q45.y, NW = rec[6];

// swap-form gate on the pack lane, all 8 packed regs
#define PACK_GATE(gi)                                                 \
    {                                                                 \
        const u64* rec = gpk + (gi) * 12;                             \
        u64 PX = rec[0], PWv = rec[5], NWv = rec[6];                  \
        ulonglong2 mm = *(const ulonglong2*)(rec + 8);                \
        u64 MY = mm.x, MYr = mm.y, MZ = rec[10];                      \
        _Pragma("unroll")                                             \
        for (int p = 0; p < 8; p++) {                                 \
            u64 R = Re[p], I = Im[p];                                 \
            u64 Rs = f2swap(R), Is = f2swap(I);                       \
            Re[p] = f2fma(NWv, Is, f2fma(MZ, Rs, f2fma(MY,  I, f2mul(PX, R)))); \
            Im[p] = f2fma(PWv, Rs, f2fma(MZ, Is, f2fma(MYr, R, f2mul(PX, I)))); \
        }                                                             \
    }

// register-pair gate over reg-bit mask (1,2,4)
#define REGPAIR_GATE(gi, mask)                                        \
    {                                                                 \
        LOADC(gi)                                                     \
        _Pragma("unroll")                                             \
        for (int p0 = 0; p0 < 8; p0++) {                              \
            if (p0 & (mask)) continue;                                \
            const int p1 = p0 | (mask);                               \
            u64 aR = Re[p0], aI = Im[p0], bR = Re[p1], bI = Im[p1];   \
            Re[p0] = f2fma(NW, bI, f2fma(PZ, bR, f2fma(NY, aI, f2mul(PX, aR)))); \
            Im[p0] = f2fma(PW, bR, f2fma(PZ, bI, f2fma(PY, aR, f2mul(PX, aI)))); \
            Re[p1] = f2fma(NW, aI, f2fma(NZ, aR, f2fma(PY, bI, f2mul(PX, bR)))); \
            Im[p1] = f2fma(PW, aR, f2fma(NZ, aI, f2fma(NY, bR, f2mul(PX, bI)))); \
        }                                                             \
    }

__global__ __launch_bounds__(THREADS, 2)
void qgen_kernel(const float* __restrict__ noise,
                 const float* __restrict__ W1, const float* __restrict__ b1,
                 const float* __restrict__ W2, const float* __restrict__ b2,
                 const float* __restrict__ W3, const float* __restrict__ b3,
                 const float* __restrict__ W4, const float* __restrict__ b4,
                 float* __restrict__ out)
{
    __shared__ __align__(16) u64 exR64[2048];
    __shared__ __align__(16) u64 exI64[2048];
    __shared__ __align__(16) u64 gpk[48 * 12];
    __shared__ float2 s_v[12][2];
    __shared__ float s_nz[12];
    __shared__ float s_h[64];
    __shared__ float s_par[NPAR];
    __shared__ float s_meas[12];
    __shared__ float s_wsum[8][12];
    __shared__ float s_h2[64];

    float* exRf = (float*)exR64;
    float* exIf = (float*)exI64;

    const int t   = threadIdx.x;
    const int bId = blockIdx.x;

    if (t < 12) s_nz[t] = noise[bId * 12 + t];
    __syncthreads();

    // ---- MLP1 ----
    if (t < 64) {
        float acc = b1[t];
        #pragma unroll
        for (int m = 0; m < 12; m++) acc += s_nz[m] * W1[m * 64 + t];
        s_h[t] = tanhf(acc);
    }
    __syncthreads();

    // ---- MLP2 ----
    if (t < NPAR) {
        float acc = b2[t];
        #pragma unroll 8
        for (int j = 0; j < 64; j++) acc += s_h[j] * W2[j * NPAR + t];
        s_par[t] = acc;
    }
    __syncthreads();

    // ---- per-gate SU(2): U = RZ(c)RY(b)RX(a) = [[gx+igy, gz+igw],[-(gz-igw), gx-igy]]
    if (t < 48) {
        float a = s_par[t * 3 + 0], b = s_par[t * 3 + 1], c = s_par[t * 3 + 2];
        float ca, sa, cb, sb, cc, sc;
        sincosf(0.5f * a, &sa, &ca);
        sincosf(0.5f * b, &sb, &cb);
        sincosf(0.5f * c, &sc, &cc);
        float x = cb * ca, y = sb * sa, z = sb * ca, w = cb * sa;
        float gx =  cc * x + sc * y;
        float gy =  cc * y - sc * x;
        float gz = -(cc * z + sc * w);
        float gw =  sc * z - cc * w;
        u64* r = gpk + t * 12;
        r[0]  = pk(gx, gx);  r[1] = pk(gy, gy);  r[2] = pk(-gy, -gy);
        r[3]  = pk(gz, gz);  r[4] = pk(-gz, -gz);
        r[5]  = pk(gw, gw);  r[6] = pk(-gw, -gw);
        r[8]  = pk(-gy, gy); r[9] = pk(gy, -gy); r[10] = pk(gz, -gz);
        if (t < 12) {   // layer-0: U|0> = (gx+igy, -(gz-igw))
            s_v[t][0] = make_float2(gx, gy);
            s_v[t][1] = make_float2(-gz, gw);
        }
    }

    // ---- per-thread addresses ----
    // Layout A: thread = i[11:4]; pack=i0 (q11); regs p=i[3:1] (q10,q9,q8)
    //   u64 unit address: UA ^ p, UA = (t<<3) ^ ((t>>1)&0xF)
    const int UA = (t << 3) ^ ((t >> 1) & 0xF);
    // Layout C: thread = (i[11:8]<<4)|i[3:0]; pack=i4 (q7); regs rC=i[7:5] (q6,q5,q4)
    //   float addr: FC0 ^ (rC*0x22) (pack partner ^0x10)
    const int FC0 = ((t >> 4) << 8) ^ (t & 0xF) ^ (((t >> 4) & 1) << 4);
    // Layout B: thread = i[7:0]; pack=i8 (q3); regs rB=i[11:9] (q2,q1,q0)
    //   float addr: FB0 ^ (rB<<9) (pack partner ^0x110)
    const int FB0 = t ^ (((t >> 5) & 1) << 1) ^ (((t >> 6) & 1) << 2)
                      ^ (((t >> 7) & 1) << 3);
    // perm scatter base (B-side): F(P(t))
    const int pB = Fful(perm12(t));

    __syncthreads();   // gpk + s_v visible

    // ---- layer 0 (gates + first ring) via product-state synthesis (layout A) ----
    u64 Re[8], Im[8];
    {
        c2 v[12][2];
        #pragma unroll
        for (int q = 0; q < 12; q++) {
            float2 a0 = s_v[q][0], a1 = s_v[q][1];
            v[q][0].r = a0.x; v[q][0].i = a0.y;
            v[q][1].r = a1.x; v[q][1].i = a1.y;
        }
        const int x2 = ((t >> 5) ^ (t >> 6)) & 1;
        const int x3 = ((t >> 4) ^ (t >> 5)) & 1;
        const int x4 = ((t >> 3) ^ (t >> 4)) & 1;
        const int x5 = ((t >> 2) ^ (t >> 3)) & 1;
        const int x6 = ((t >> 1) ^ (t >> 2)) & 1;
        const int x7 = ( t       ^ (t >> 1)) & 1;
        const int e0 = (t >> 7) & 1;                 // i11
        const int e1 = ((t >> 6) ^ (t >> 7)) & 1;    // i10^i11
        const int e4 = t & 1;                        // i4

        c2 base = cmul(cmul(cmul(v[2][x2], v[3][x3]), cmul(v[4][x4], v[5][x5])),
                       cmul(v[6][x6], v[7][x7]));
        c2 base2[2];
        base2[0] = cmul(base, v[8][e4]);
        base2[1] = cmul(base, v[8][e4 ^ 1]);

        c2 A[2];
        A[0] = cmul(v[0][e0],     v[1][e1]);
        A[1] = cmul(v[0][e0 ^ 1], v[1][e1 ^ 1]);
        c2 B[4];
        B[0] = cmul(A[0], v[11][0]);
        B[1] = cmul(A[1], v[11][1]);
        B[2] = cmul(A[0], v[11][1]);
        B[3] = cmul(A[1], v[11][0]);
        c2 C[8];
        #pragma unroll
        for (int k2 = 0; k2 < 2; k2++)
            #pragma unroll
            for (int j = 0; j < 4; j++)
                C[k2 * 4 + j] = cmul(B[j], v[10][((j >> 1) & 1) ^ k2]);
        #pragma unroll
        for (int k3 = 0; k3 < 2; k3++)
            #pragma unroll
            for (int j = 0; j < 8; j += 2) {
                c2 d0 = cmul(cmul(C[j],     v[9][((j >> 2) & 1) ^ k3]), base2[k3]);
                c2 d1 = cmul(cmul(C[j + 1], v[9][(((j+1) >> 2) & 1) ^ k3]), base2[k3]);
                int p = (k3 * 8 + j) >> 1;
                Re[p] = pk(d0.r, d1.r);
                Im[p] = pk(d0.i, d1.i);
            }
    }

    // ---- layers 1..3 : A gates -> C gates -> B gates -> (perm) ----
    #pragma unroll 1
    for (int l = 1; l < DEPTH; l++) {
        // A section: q11 pack, q10/q9/q8 regpair
        PACK_GATE(l * 12 + 11)
        REGPAIR_GATE(l * 12 + 10, 1)
        REGPAIR_GATE(l * 12 + 9, 2)
        REGPAIR_GATE(l * 12 + 8, 4)

        // exchange A -> C
        __syncthreads();
        #pragma unroll
        for (int p = 0; p < 8; p++) {
            exR64[UA ^ p] = Re[p];
            exI64[UA ^ p] = Im[p];
        }
        __syncthreads();
        #pragma unroll
        for (int r = 0; r < 8; r++) {
            const int a0 = FC0 ^ (r * 0x22);
            const int a1 = a0 ^ 0x10;
            Re[r] = pk(exRf[a0], exRf[a1]);
            Im[r] = pk(exIf[a0], exIf[a1]);
        }

        // C section: q7 pack, q6/q5/q4 regpair
        PACK_GATE(l * 12 + 7)
        REGPAIR_GATE(l * 12 + 6, 1)
        REGPAIR_GATE(l * 12 + 5, 2)
        REGPAIR_GATE(l * 12 + 4, 4)

        // exchange C -> B
        __syncthreads();
        #pragma unroll
        for (int r = 0; r < 8; r++) {
            float r0, r1, i0v, i1v;
            upk(Re[r], r0, r1);
            upk(Im[r], i0v, i1v);
            const int a0 = FC0 ^ (r * 0x22);
            const int a1 = a0 ^ 0x10;
            exRf[a0] = r0;  exIf[a0] = i0v;
            exRf[a1] = r1;  exIf[a1] = i1v;
        }
        __syncthreads();
        #pragma unroll
        for (int r = 0; r < 8; r++) {
            const int a0 = FB0 ^ (r << 9);
            const int a1 = a0 ^ 0x110;
            Re[r] = pk(exRf[a0], exRf[a1]);
            Im[r] = pk(exIf[a0], exIf[a1]);
        }

        // B section: q3 pack, q2/q1/q0 regpair
        PACK_GATE(l * 12 + 3)
        REGPAIR_GATE(l * 12 + 2, 1)
        REGPAIR_GATE(l * 12 + 1, 2)
        REGPAIR_GATE(l * 12 + 0, 4)

        if (l == DEPTH - 1) break;   // final ring folded into measurement signs

        // perm scatter B -> A
        __syncthreads();
        #pragma unroll
        for (int r = 0; r < 8; r++) {
            float r0, r1, i0v, i1v;
            upk(Re[r], r0, r1);
            upk(Im[r], i0v, i1v);
            const int a0 = pB ^ Fful(perm12((2 * r)     << 8));
            const int a1 = pB ^ Fful(perm12((2 * r + 1) << 8));
            exRf[a0] = r0;  exIf[a0] = i0v;
            exRf[a1] = r1;  exIf[a1] = i1v;
        }
        __syncthreads();
        #pragma unroll
        for (int p = 0; p < 8; p++) {
            Re[p] = exR64[UA ^ p];
            Im[p] = exI64[UA ^ p];
        }
    }

    // ---- <Z_q> in layout B; final ring folded into suffix-parity signs ----
    // s = (m<<8)|t, pack=s8 (df), r bits: r0=s9, r1=s10, r2=s11
    // sign_q = parity(d_{11-q}) with d = P(s):
    //   q=0: s0..s10 -> parity(t&0xFF)^parity(r&3), df
    //   q=1: s10,s11 -> r&6, sm ; q=2: s9..s11 -> r&7, sm
    //   q>=3: s(11-q)..s11 -> r&7 & s8 (df) with thread mask on t bits (11-q)..7
    float U0 = 0.f, U1 = 0.f, U2 = 0.f, U3 = 0.f;
    #pragma unroll
    for (int r = 0; r < 8; r++) {
        u64 p2 = f2fma(Im[r], Im[r], f2mul(Re[r], Re[r]));
        float pl, ph; upk(p2, pl, ph);
        float sm = pl + ph, df = pl - ph;
        U0 += (__popc(r & 3) & 1) ? -df : df;
        U1 += (__popc(r & 6) & 1) ? -sm : sm;
        U2 += (__popc(r & 7) & 1) ? -sm : sm;
        U3 += (__popc(r & 7) & 1) ? -df : df;
    }
    float c[12];
    c[0] = (__popc(t & 0xFF) & 1) ? -U0 : U0;
    c[1] = U1;
    c[2] = U2;
    c[3] = U3;
    {
        const int masks[8] = {0x80, 0xC0, 0xE0, 0xF0, 0xF8, 0xFC, 0xFE, 0xFF};
        #pragma unroll
        for (int q = 4; q < 12; q++)
            c[q] = (__popc(t & masks[q - 4]) & 1) ? -U3 : U3;
    }

    #pragma unroll
    for (int s = 16; s >= 1; s >>= 1) {
        #pragma unroll
        for (int q = 0; q < 12; q++)
            c[q] += __shfl_xor_sync(0xffffffffu, c[q], s);
    }
    const int warp = t >> 5, lane = t & 31;
    if (lane == 0) {
        #pragma unroll
        for (int q = 0; q < 12; q++) s_wsum[warp][q] = c[q];
    }
    __syncthreads();
    if (t < 12) {
        float m = 0.f;
        #pragma unroll
        for (int w = 0; w < 8; w++) m += s_wsum[w][t];
        s_meas[t] = m;
    }
    __syncthreads();

    // ---- MLP3 ----
    if (t < 64) {
        float acc = b3[t];
        #pragma unroll
        for (int q = 0; q < 12; q++) acc += s_meas[q] * W3[q * 64 + t];
        s_h2[t] = tanhf(acc);
    }
    __syncthreads();

    // ---- out ----
    if (t < 2) {
        float acc = b4[t];
        #pragma unroll 8
        for (int j = 0; j < 64; j++) acc += s_h2[j] * W4[j * 2 + t];
        out[bId * 2 + t] = acc;
    }
}

extern "C" void kernel_launch(void* const* d_in, const int* in_sizes, int n_in,
                              void* d_out, int out_size)
{
    (void)n_in; (void)out_size;
    const float* noise = (const float*)d_in[0];
    const float* W1    = (const float*)d_in[1];
    const float* b1    = (const float*)d_in[2];
    const float* W2    = (const float*)d_in[3];
    const float* b2    = (const float*)d_in[4];
    const float* W3    = (const float*)d_in[5];
    const float* b3    = (const float*)d_in[6];
    const float* W4    = (const float*)d_in[7];
    const float* b4    = (const float*)d_in[8];
    float* out = (float*)d_out;

    const int B = in_sizes[0] / NQ;
    qgen_kernel<<<B, THREADS>>>(noise, W1, b1, W2, b2, W3, b3, W4, b4, out);
}